// round 13
// baseline (speedup 1.0000x reference)
#include <cuda_runtime.h>
#include <cuda_bf16.h>
#include <cstdint>

// ============================ helpers ============================
__device__ __forceinline__ uint32_t smem_u32(const void* p) {
    uint32_t a;
    asm("{ .reg .u64 t; cvta.to.shared.u64 t, %1; cvt.u32.u64 %0, t; }" : "=r"(a) : "l"(p));
    return a;
}
__device__ __forceinline__ uint32_t sw128(uint32_t o) { return o ^ ((o >> 3) & 0x70); }

#define LDSM_X4(r0, r1, r2, r3, a) \
    asm volatile("ldmatrix.sync.aligned.m8n8.x4.shared.b16 {%0,%1,%2,%3}, [%4];" \
                 : "=r"(r0), "=r"(r1), "=r"(r2), "=r"(r3) : "r"(a))

#define CP_ASYNC16(dst, src) \
    asm volatile("cp.async.cg.shared.global [%0], [%1], 16;" :: "r"(dst), "l"(src))
#define CP_COMMIT() asm volatile("cp.async.commit_group;")
#define CP_WAIT0()  asm volatile("cp.async.wait_group 0;")

__device__ __forceinline__ void mma16816(float* c, const uint32_t* a, uint32_t b0, uint32_t b1) {
    asm volatile(
        "mma.sync.aligned.m16n8k16.row.col.f32.bf16.bf16.f32 "
        "{%0,%1,%2,%3}, {%4,%5,%6,%7}, {%8,%9}, {%0,%1,%2,%3};"
        : "+f"(c[0]), "+f"(c[1]), "+f"(c[2]), "+f"(c[3])
        : "r"(a[0]), "r"(a[1]), "r"(a[2]), "r"(a[3]), "r"(b0), "r"(b1));
}

// ============================ device scratch ============================
// W repacked: 12 chunk images, each [128 n-rows][64 bf16 k], SW128 swizzled, 16KB
__device__ __align__(16) unsigned char g_Wsw[12 * 16384];
// Normalized embeddings: tiles 0..31 = Q; 32..1055 = doc tile slots
// slot layout for docs: 32 + (side*128 + batch)*4 + i  (compacted rows)
__device__ __align__(16) unsigned char g_norm[1056 * 32768];
// Compaction: indices of unmasked rows per (side,batch), and counts
__device__ unsigned short g_idx[256][512];
__device__ int g_cnt[256];
// Per-doc-tile partial col-maxima: row = bs*4 + slot
__device__ float g_part[1024][32];

// ============================ Kernel 0: W repack + mask compaction ==========
// grid 640: blocks 0..383 repack W; blocks 384..639 compact masks (warp 0 only)
__global__ void k_prep(const float* __restrict__ W,
                       const int* __restrict__ pdm, const int* __restrict__ ndm) {
    if (blockIdx.x < 384) {
        int idx = blockIdx.x * 256 + threadIdx.x;   // 0 .. 98303
        int c = idx >> 13;                           // chunk (0..11)
        int rem = idx & 8191;
        int j = rem >> 7;                            // k within chunk (0..63)
        int n = rem & 127;                           // output dim
        float v = W[(c * 64 + j) * 128 + n];
        __nv_bfloat16 bv = __float2bfloat16(v);
        *(__nv_bfloat16*)(g_Wsw + c * 16384 + sw128((uint32_t)(n * 128 + j * 2))) = bv;
    } else if (threadIdx.x < 32) {
        const int bs = blockIdx.x - 384;             // side*128 + batch
        const int* m = (bs < 128) ? (pdm + bs * 512) : (ndm + (bs - 128) * 512);
        const int lane = threadIdx.x;
        int loc[16], cnt = 0;
        #pragma unroll
        for (int i = 0; i < 16; ++i) { loc[i] = m[lane * 16 + i]; cnt += loc[i]; }
        int off = cnt;
        #pragma unroll
        for (int d = 1; d < 32; d <<= 1) {
            int v = __shfl_up_sync(0xFFFFFFFFu, off, d);
            if (lane >= d) off += v;
        }
        int pos = off - cnt;
        int total = __shfl_sync(0xFFFFFFFFu, off, 31);
        #pragma unroll
        for (int i = 0; i < 16; ++i)
            if (loc[i]) g_idx[bs][pos++] = (unsigned short)(lane * 16 + i);
        if (lane == 31) g_cnt[bs] = total;
    }
}

// ============================ Kernel 1: projection + bias + L2 norm ========
// grid 1056, block 256 (8 warps: 4 M x 2 N). Each CTA: M=128 rows, N=128, K=768.
// Blocks 0..31: Q tiles (dense). Blocks 32..1055: doc tile slots over COMPACTED
// (unmasked) rows; slots beyond the batch's count exit immediately. Pad rows in
// partial tiles are stored as exact zeros.
// A prefetched into raw float4 regs (LDG only -- conversion DEFERRED to next
// iteration's store phase); B via double-buffered cp.async from L2-resident W.
// launch_bounds(256,2): occupancy-2 experiment on the deferred-convert loop.
// smem: [0..512) bias fp32, [512..1536) rowsq fp32[2][128],
//       [2048) A buf0 16KB, [18432) A buf1, [34816) B buf0 16KB, [51200) B buf1
__global__ void __launch_bounds__(256, 2) k_proj(
    const float* __restrict__ qh, const float* __restrict__ pdh, const float* __restrict__ ndh,
    const float* __restrict__ bias)
{
    extern __shared__ __align__(1024) unsigned char smem[];
    uint32_t sb = smem_u32(smem);
    const int tid = threadIdx.x, wid = tid >> 5, lid = tid & 31;
    const int wm = wid & 3, wn = wid >> 2;
    const int tg = lid & 3, gid = lid >> 2;
    const int t = blockIdx.x;

    const float* src;
    int bs = 0, rbase = 0, cnt = 0;
    if (t < 32) {
        src = qh + (size_t)t * 98304;   // dense 128-row tile
        cnt = 1 << 30;
    } else {
        const int slot = t - 32;
        bs = slot >> 2;                  // side*128 + batch
        rbase = (slot & 3) * 128;        // compacted-row base of this tile
        cnt = g_cnt[bs];
        if (rbase >= cnt) return;        // empty slot
        src = (bs < 128) ? (pdh + (size_t)bs * 393216)
                         : (ndh + (size_t)(bs - 128) * 393216);
    }

    if (tid < 128) ((float*)smem)[tid] = bias[tid];

    const int fr = tid >> 4, fseg = tid & 15;   // A-load row / 16B-segment
    // gather row indices for this thread's 8 rows (constant across chunks)
    int rids[8];
    #pragma unroll
    for (int u = 0; u < 8; ++u) {
        int row = fr + u * 16;
        if (t < 32) rids[u] = row;
        else {
            int cr = rbase + row;
            rids[u] = (cr < cnt) ? (int)g_idx[bs][cr] : (int)g_idx[bs][0];
        }
    }

    float c[2][8][4];
    #pragma unroll
    for (int mi = 0; mi < 2; ++mi)
        #pragma unroll
        for (int ni = 0; ni < 8; ++ni)
            #pragma unroll
            for (int r = 0; r < 4; ++r) c[mi][ni][r] = 0.f;

    const int lrow = (lid & 7) + ((lid >> 3) & 1) * 8;   // ldmatrix row within 16
    const int lhalf = lid >> 4;                           // ldmatrix k-half

    // prologue: B chunk 0 via cp.async, A chunk 0 into raw float4 registers
    {
        uint32_t bdst = sb + 34816;
        const unsigned char* bsrc = g_Wsw;
        #pragma unroll
        for (int u = 0; u < 4; ++u)
            CP_ASYNC16(bdst + (tid + u * 256) * 16, bsrc + (size_t)(tid + u * 256) * 16);
        CP_COMMIT();
    }
    float4 areg[8];
    #pragma unroll
    for (int u = 0; u < 8; ++u)
        areg[u] = *(const float4*)(src + (size_t)rids[u] * 768 + fseg * 4);

    for (int it = 0; it < 12; ++it) {
        const int buf = it & 1;
        const uint32_t Ao = 2048 + buf * 16384;
        // convert + store prefetched A regs -> smem (bf16, SW128)
        #pragma unroll
        for (int u = 0; u < 8; ++u) {
            __nv_bfloat162 lo = __floats2bfloat162_rn(areg[u].x, areg[u].y);
            __nv_bfloat162 hi = __floats2bfloat162_rn(areg[u].z, areg[u].w);
            uint2 pk; pk.x = *(uint32_t*)&lo; pk.y = *(uint32_t*)&hi;
            *(uint2*)(smem + Ao + sw128((uint32_t)((fr + u * 16) * 128 + fseg * 8))) = pk;
        }
        CP_WAIT0();            // B(it) landed
        __syncthreads();       // A stores + B visible; all MMA(it-1) reads done
        if (it < 11) {
            // stream B(it+1) into the other buffer (overlaps with MMA below)
            uint32_t bdst = sb + 34816 + (buf ^ 1) * 16384;
            const unsigned char* bsrc = g_Wsw + (size_t)(it + 1) * 16384;
            #pragma unroll
            for (int u = 0; u < 4; ++u)
                CP_ASYNC16(bdst + (tid + u * 256) * 16, bsrc + (size_t)(tid + u * 256) * 16);
            CP_COMMIT();
            // prefetch A(it+1): LDG only, no dependent cvt -> warp reaches MMAs
            #pragma unroll
            for (int u = 0; u < 8; ++u)
                areg[u] = *(const float4*)(src + (size_t)rids[u] * 768 + (it + 1) * 64 + fseg * 4);
        }
        // MMA on buf
        const uint32_t Ab = sb + Ao, Bb = sb + 34816 + buf * 16384;
        #pragma unroll
        for (int ks = 0; ks < 4; ++ks) {
            const int lseg = (ks * 2 + lhalf) * 16;
            uint32_t af[2][4];
            #pragma unroll
            for (int mi = 0; mi < 2; ++mi) {
                int r = wm * 32 + mi * 16 + lrow;
                LDSM_X4(af[mi][0], af[mi][1], af[mi][2], af[mi][3],
                        Ab + sw128((uint32_t)(r * 128 + lseg)));
            }
            uint32_t bf[8][2];
            #pragma unroll
            for (int nb = 0; nb < 4; ++nb) {
                int n = wn * 64 + nb * 16 + lrow;
                uint32_t q0, q1, q2, q3;
                LDSM_X4(q0, q1, q2, q3, Bb + sw128((uint32_t)(n * 128 + lseg)));
                bf[nb * 2][0] = q0; bf[nb * 2][1] = q2;
                bf[nb * 2 + 1][0] = q1; bf[nb * 2 + 1][1] = q3;
            }
            #pragma unroll
            for (int mi = 0; mi < 2; ++mi)
                #pragma unroll
                for (int ni = 0; ni < 8; ++ni)
                    mma16816(c[mi][ni], af[mi], bf[ni][0], bf[ni][1]);
        }
    }

    // ---------------- epilogue: bias, row sum-of-squares, normalize, store ---
    const float* bsm = (const float*)smem;
    float* rowsq = (float*)(smem + 512);
    #pragma unroll
    for (int mi = 0; mi < 2; ++mi)
        #pragma unroll
        for (int rp = 0; rp < 2; ++rp) {
            float s = 0.f;
            #pragma unroll
            for (int ni = 0; ni < 8; ++ni)
                #pragma unroll
                for (int c0 = 0; c0 < 2; ++c0) {
                    int col = wn * 64 + ni * 8 + tg * 2 + c0;
                    float x = c[mi][ni][rp * 2 + c0] + bsm[col];
                    c[mi][ni][rp * 2 + c0] = x;
                    s += x * x;
                }
            s += __shfl_xor_sync(0xFFFFFFFFu, s, 1);
            s += __shfl_xor_sync(0xFFFFFFFFu, s, 2);
            int row = wm * 32 + mi * 16 + gid + rp * 8;
            if (tg == 0) rowsq[wn * 128 + row] = s;
        }
    __syncthreads();

    unsigned char* dst = g_norm + (size_t)t * 32768 + (size_t)wn * 16384;
    #pragma unroll
    for (int mi = 0; mi < 2; ++mi)
        #pragma unroll
        for (int rp = 0; rp < 2; ++rp) {
            int row = wm * 32 + mi * 16 + gid + rp * 8;
            float tot = rowsq[row] + rowsq[128 + row];
            // pad rows (beyond compacted count) become exact zero vectors
            float mf = (t < 32 || rbase + row < cnt) ? 1.f : 0.f;
            float sc = mf / fmaxf(sqrtf(tot), 1e-12f);
            #pragma unroll
            for (int ni = 0; ni < 8; ++ni) {
                float x0 = c[mi][ni][rp * 2]     * sc;
                float x1 = c[mi][ni][rp * 2 + 1] * sc;
                __nv_bfloat162 p2 = __floats2bfloat162_rn(x0, x1);
                *(uint32_t*)(dst + sw128((uint32_t)(row * 128 + (ni * 8 + tg * 2) * 2))) =
                    *(uint32_t*)&p2;
            }
        }
}

// ============================ Kernel 2: MaxSim (per-tile) ===================
// grid 1024 (= bs*4 + slot), block 256 (8 warps x 16 doc rows). One doc tile
// per CTA -> ~640 active CTAs in one wave, no serial tile loop. Partial
// per-query column maxima to g_part[blockIdx.x].
// smem: [0..1024) reduce buf fp32[8][32],
//       [1024..9216) Q tile (2 x 4KB SW128 sub-images), [9216..41984) doc tile
__global__ void __launch_bounds__(256) k_maxsim()
{
    extern __shared__ __align__(1024) unsigned char smem[];
    uint32_t sb = smem_u32(smem);
    const int tid = threadIdx.x, wid = tid >> 5, lid = tid & 31;
    const int tg = lid & 3;
    const int bs = blockIdx.x >> 2, slot = blockIdx.x & 3;
    const int cnt = g_cnt[bs];
    if (slot * 128 >= cnt) return;              // empty tile slot
    const int b = bs & 127;                      // batch

    // doc tile (32KB) + Q slice (8KB) via one cp.async group
    {
        uint32_t dd = sb + 9216;
        const unsigned char* ds = g_norm + (size_t)(32 + bs * 4 + slot) * 32768;
        #pragma unroll
        for (int u = 0; u < 8; ++u)
            CP_ASYNC16(dd + (tid + u * 256) * 16, ds + (size_t)(tid + u * 256) * 16);
        const unsigned char* qsrc = g_norm + (size_t)(b >> 2) * 32768 + (size_t)(b & 3) * 4096;
        #pragma unroll
        for (int ch = 0; ch < 2; ++ch)
            CP_ASYNC16(sb + 1024 + ch * 4096 + tid * 16, qsrc + ch * 16384 + (size_t)tid * 16);
        CP_COMMIT();
    }
    CP_WAIT0();
    __syncthreads();

    const int lrow = (lid & 7) + ((lid >> 3) & 1) * 8;
    const int lhalf = lid >> 4;
    const int wr = wid * 16;                    // this warp's 16 doc rows

    float cc[4][4];
    #pragma unroll
    for (int ni = 0; ni < 4; ++ni)
        #pragma unroll
        for (int r = 0; r < 4; ++r) cc[ni][r] = 0.f;

    #pragma unroll
    for (int ks = 0; ks < 8; ++ks) {
        const int chunk = ks >> 2, kk = ks & 3;
        const int lseg = (kk * 2 + lhalf) * 16;
        uint32_t af[4];
        LDSM_X4(af[0], af[1], af[2], af[3],
                sb + 9216 + chunk * 16384 + sw128((uint32_t)((wr + lrow) * 128 + lseg)));
        uint32_t bf[4][2];
        #pragma unroll
        for (int nb = 0; nb < 2; ++nb) {
            int n = nb * 16 + lrow;
            uint32_t q0, q1, q2, q3;
            LDSM_X4(q0, q1, q2, q3,
                    sb + 1024 + chunk * 4096 + sw128((uint32_t)(n * 128 + lseg)));
            bf[nb * 2][0] = q0; bf[nb * 2][1] = q2;
            bf[nb * 2 + 1][0] = q1; bf[nb * 2 + 1][1] = q3;
        }
        #pragma unroll
        for (int ni = 0; ni < 4; ++ni)
            mma16816(cc[ni], af, bf[ni][0], bf[ni][1]);
    }

    // per-query max over this warp's 16 doc rows
    float* red = (float*)smem;   // [8 warps][32 queries]
    #pragma unroll
    for (int ni = 0; ni < 4; ++ni)
        #pragma unroll
        for (int c0 = 0; c0 < 2; ++c0) {
            float m = fmaxf(cc[ni][c0], cc[ni][c0 + 2]);
            m = fmaxf(m, __shfl_xor_sync(0xFFFFFFFFu, m, 4));
            m = fmaxf(m, __shfl_xor_sync(0xFFFFFFFFu, m, 8));
            m = fmaxf(m, __shfl_xor_sync(0xFFFFFFFFu, m, 16));
            if ((lid >> 2) == 0) red[wid * 32 + ni * 8 + tg * 2 + c0] = m;
        }
    __syncthreads();
    if (tid < 32) {
        float m = red[tid];
        #pragma unroll
        for (int w = 1; w < 8; ++w) m = fmaxf(m, red[w * 32 + tid]);
        g_part[blockIdx.x][tid] = m;
    }
}

// ============================ Kernel 3: final reduce ========================
// grid 256 (= batch*2), block 32: max over active tiles per query, clamp for
// masked zero rows, sum over 32 queries.
__global__ void k_final(float* __restrict__ out) {
    const int b = blockIdx.x >> 1, s = blockIdx.x & 1;
    const int bs = s * 128 + b;
    const int cnt = g_cnt[bs];
    const int nt = (cnt + 127) >> 7;
    const int q = threadIdx.x;
    float m = -3.0e38f;
    for (int i = 0; i < nt; ++i)
        m = fmaxf(m, g_part[bs * 4 + i][q]);
    if (cnt < 512) m = fmaxf(m, 0.f);   // masked tokens are exact zero vectors
    #pragma unroll
    for (int off = 16; off; off >>= 1) m += __shfl_xor_sync(0xFFFFFFFFu, m, off);
    if (q == 0) out[b * 2 + s] = m;
}

// ============================ launch ============================
extern "C" void kernel_launch(void* const* d_in, const int* in_sizes, int n_in,
                              void* d_out, int out_size) {
    const float* qh  = (const float*)d_in[0];
    const float* pdh = (const float*)d_in[1];
    const float* ndh = (const float*)d_in[2];
    const float* W   = (const float*)d_in[3];
    const float* b   = (const float*)d_in[4];
    const int*   pdm = (const int*)d_in[5];
    const int*   ndm = (const int*)d_in[6];
    float* out = (float*)d_out;

    // dyn smem > 48KB needs an explicit opt-in
    cudaFuncSetAttribute(k_proj,   cudaFuncAttributeMaxDynamicSharedMemorySize, 67584);
    cudaFuncSetAttribute(k_maxsim, cudaFuncAttributeMaxDynamicSharedMemorySize, 41984);

    k_prep<<<640, 256>>>(W, pdm, ndm);
    k_proj<<<1056, 256, 67584>>>(qh, pdh, ndh, b);
    k_maxsim<<<1024, 256, 41984>>>();
    k_final<<<256, 32>>>(out);
}

// round 14
// speedup vs baseline: 1.3796x; 1.3796x over previous
#include <cuda_runtime.h>
#include <cuda_bf16.h>
#include <cstdint>

// ============================ helpers ============================
__device__ __forceinline__ uint32_t smem_u32(const void* p) {
    uint32_t a;
    asm("{ .reg .u64 t; cvta.to.shared.u64 t, %1; cvt.u32.u64 %0, t; }" : "=r"(a) : "l"(p));
    return a;
}
__device__ __forceinline__ uint32_t sw128(uint32_t o) { return o ^ ((o >> 3) & 0x70); }

#define LDSM_X4(r0, r1, r2, r3, a) \
    asm volatile("ldmatrix.sync.aligned.m8n8.x4.shared.b16 {%0,%1,%2,%3}, [%4];" \
                 : "=r"(r0), "=r"(r1), "=r"(r2), "=r"(r3) : "r"(a))

#define CP_ASYNC16(dst, src) \
    asm volatile("cp.async.cg.shared.global [%0], [%1], 16;" :: "r"(dst), "l"(src))
#define CP_COMMIT() asm volatile("cp.async.commit_group;")
#define CP_WAIT0()  asm volatile("cp.async.wait_group 0;")

__device__ __forceinline__ void mma16816(float* c, const uint32_t* a, uint32_t b0, uint32_t b1) {
    asm volatile(
        "mma.sync.aligned.m16n8k16.row.col.f32.bf16.bf16.f32 "
        "{%0,%1,%2,%3}, {%4,%5,%6,%7}, {%8,%9}, {%0,%1,%2,%3};"
        : "+f"(c[0]), "+f"(c[1]), "+f"(c[2]), "+f"(c[3])
        : "r"(a[0]), "r"(a[1]), "r"(a[2]), "r"(a[3]), "r"(b0), "r"(b1));
}

// ============================ device scratch ============================
// W repacked: 12 chunk images, each [128 n-rows][64 bf16 k], SW128 swizzled, 16KB
__device__ __align__(16) unsigned char g_Wsw[12 * 16384];
// Normalized embeddings: tiles 0..31 = Q; 32..1055 = doc tile slots
// slot layout for docs: 32 + (side*128 + batch)*4 + i  (compacted rows)
__device__ __align__(16) unsigned char g_norm[1056 * 32768];
// Compaction: indices of unmasked rows per (side,batch), and counts
__device__ unsigned short g_idx[256][512];
__device__ int g_cnt[256];

// ============================ Kernel 0: W repack + mask compaction ==========
// grid 640: blocks 0..383 repack W; blocks 384..639 compact masks (warp 0 only)
__global__ void k_prep(const float* __restrict__ W,
                       const int* __restrict__ pdm, const int* __restrict__ ndm) {
    if (blockIdx.x < 384) {
        int idx = blockIdx.x * 256 + threadIdx.x;   // 0 .. 98303
        int c = idx >> 13;                           // chunk (0..11)
        int rem = idx & 8191;
        int j = rem >> 7;                            // k within chunk (0..63)
        int n = rem & 127;                           // output dim
        float v = W[(c * 64 + j) * 128 + n];
        __nv_bfloat16 bv = __float2bfloat16(v);
        *(__nv_bfloat16*)(g_Wsw + c * 16384 + sw128((uint32_t)(n * 128 + j * 2))) = bv;
    } else if (threadIdx.x < 32) {
        const int bs = blockIdx.x - 384;             // side*128 + batch
        const int* m = (bs < 128) ? (pdm + bs * 512) : (ndm + (bs - 128) * 512);
        const int lane = threadIdx.x;
        int loc[16], cnt = 0;
        #pragma unroll
        for (int i = 0; i < 16; ++i) { loc[i] = m[lane * 16 + i]; cnt += loc[i]; }
        int off = cnt;
        #pragma unroll
        for (int d = 1; d < 32; d <<= 1) {
            int v = __shfl_up_sync(0xFFFFFFFFu, off, d);
            if (lane >= d) off += v;
        }
        int pos = off - cnt;
        int total = __shfl_sync(0xFFFFFFFFu, off, 31);
        #pragma unroll
        for (int i = 0; i < 16; ++i)
            if (loc[i]) g_idx[bs][pos++] = (unsigned short)(lane * 16 + i);
        if (lane == 31) g_cnt[bs] = total;
    }
}

// ============================ Kernel 1: projection + bias + L2 norm ========
// grid 1056, block 256 (8 warps: 4 M x 2 N). Each CTA: M=128 rows, N=128, K=768.
// Blocks 0..31: Q tiles (dense). Blocks 32..1055: doc tile slots over COMPACTED
// (unmasked) rows; slots beyond the batch's count exit immediately. Pad rows in
// partial tiles are stored as exact zeros.
// A prefetched into raw float4 regs (LDG only -- conversion DEFERRED to next
// iteration's store phase so the warp reaches the MMAs without stalling);
// B via double-buffered cp.async from L2-resident pre-swizzled W.
// NO occupancy forcing: the register budget (accum 64 + prefetch 32 + frags)
// makes 1 CTA/SM with no spills the proven optimum (R6/R13 both regressed).
// smem: [0..512) bias fp32, [512..1536) rowsq fp32[2][128],
//       [2048) A buf0 16KB, [18432) A buf1, [34816) B buf0 16KB, [51200) B buf1
__global__ void __launch_bounds__(256) k_proj(
    const float* __restrict__ qh, const float* __restrict__ pdh, const float* __restrict__ ndh,
    const float* __restrict__ bias)
{
    extern __shared__ __align__(1024) unsigned char smem[];
    uint32_t sb = smem_u32(smem);
    const int tid = threadIdx.x, wid = tid >> 5, lid = tid & 31;
    const int wm = wid & 3, wn = wid >> 2;
    const int tg = lid & 3, gid = lid >> 2;
    const int t = blockIdx.x;

    const float* src;
    int bs = 0, rbase = 0, cnt = 0;
    if (t < 32) {
        src = qh + (size_t)t * 98304;   // dense 128-row tile
        cnt = 1 << 30;
    } else {
        const int slot = t - 32;
        bs = slot >> 2;                  // side*128 + batch
        rbase = (slot & 3) * 128;        // compacted-row base of this tile
        cnt = g_cnt[bs];
        if (rbase >= cnt) return;        // empty slot
        src = (bs < 128) ? (pdh + (size_t)bs * 393216)
                         : (ndh + (size_t)(bs - 128) * 393216);
    }

    if (tid < 128) ((float*)smem)[tid] = bias[tid];

    const int fr = tid >> 4, fseg = tid & 15;   // A-load row / 16B-segment
    // gather row indices for this thread's 8 rows (constant across chunks)
    int rids[8];
    #pragma unroll
    for (int u = 0; u < 8; ++u) {
        int row = fr + u * 16;
        if (t < 32) rids[u] = row;
        else {
            int cr = rbase + row;
            rids[u] = (cr < cnt) ? (int)g_idx[bs][cr] : (int)g_idx[bs][0];
        }
    }

    float c[2][8][4];
    #pragma unroll
    for (int mi = 0; mi < 2; ++mi)
        #pragma unroll
        for (int ni = 0; ni < 8; ++ni)
            #pragma unroll
            for (int r = 0; r < 4; ++r) c[mi][ni][r] = 0.f;

    const int lrow = (lid & 7) + ((lid >> 3) & 1) * 8;   // ldmatrix row within 16
    const int lhalf = lid >> 4;                           // ldmatrix k-half

    // prologue: B chunk 0 via cp.async, A chunk 0 into raw float4 registers
    {
        uint32_t bdst = sb + 34816;
        const unsigned char* bsrc = g_Wsw;
        #pragma unroll
        for (int u = 0; u < 4; ++u)
            CP_ASYNC16(bdst + (tid + u * 256) * 16, bsrc + (size_t)(tid + u * 256) * 16);
        CP_COMMIT();
    }
    float4 areg[8];
    #pragma unroll
    for (int u = 0; u < 8; ++u)
        areg[u] = *(const float4*)(src + (size_t)rids[u] * 768 + fseg * 4);

    for (int it = 0; it < 12; ++it) {
        const int buf = it & 1;
        const uint32_t Ao = 2048 + buf * 16384;
        // convert + store prefetched A regs -> smem (bf16, SW128)
        #pragma unroll
        for (int u = 0; u < 8; ++u) {
            __nv_bfloat162 lo = __floats2bfloat162_rn(areg[u].x, areg[u].y);
            __nv_bfloat162 hi = __floats2bfloat162_rn(areg[u].z, areg[u].w);
            uint2 pk; pk.x = *(uint32_t*)&lo; pk.y = *(uint32_t*)&hi;
            *(uint2*)(smem + Ao + sw128((uint32_t)((fr + u * 16) * 128 + fseg * 8))) = pk;
        }
        CP_WAIT0();            // B(it) landed
        __syncthreads();       // A stores + B visible; all MMA(it-1) reads done
        if (it < 11) {
            // stream B(it+1) into the other buffer (overlaps with MMA below)
            uint32_t bdst = sb + 34816 + (buf ^ 1) * 16384;
            const unsigned char* bsrc = g_Wsw + (size_t)(it + 1) * 16384;
            #pragma unroll
            for (int u = 0; u < 4; ++u)
                CP_ASYNC16(bdst + (tid + u * 256) * 16, bsrc + (size_t)(tid + u * 256) * 16);
            CP_COMMIT();
            // prefetch A(it+1): LDG only, no dependent cvt -> warp reaches MMAs
            #pragma unroll
            for (int u = 0; u < 8; ++u)
                areg[u] = *(const float4*)(src + (size_t)rids[u] * 768 + (it + 1) * 64 + fseg * 4);
        }
        // MMA on buf
        const uint32_t Ab = sb + Ao, Bb = sb + 34816 + buf * 16384;
        #pragma unroll
        for (int ks = 0; ks < 4; ++ks) {
            const int lseg = (ks * 2 + lhalf) * 16;
            uint32_t af[2][4];
            #pragma unroll
            for (int mi = 0; mi < 2; ++mi) {
                int r = wm * 32 + mi * 16 + lrow;
                LDSM_X4(af[mi][0], af[mi][1], af[mi][2], af[mi][3],
                        Ab + sw128((uint32_t)(r * 128 + lseg)));
            }
            uint32_t bf[8][2];
            #pragma unroll
            for (int nb = 0; nb < 4; ++nb) {
                int n = wn * 64 + nb * 16 + lrow;
                uint32_t q0, q1, q2, q3;
                LDSM_X4(q0, q1, q2, q3, Bb + sw128((uint32_t)(n * 128 + lseg)));
                bf[nb * 2][0] = q0; bf[nb * 2][1] = q2;
                bf[nb * 2 + 1][0] = q1; bf[nb * 2 + 1][1] = q3;
            }
            #pragma unroll
            for (int mi = 0; mi < 2; ++mi)
                #pragma unroll
                for (int ni = 0; ni < 8; ++ni)
                    mma16816(c[mi][ni], af[mi], bf[ni][0], bf[ni][1]);
        }
    }

    // ---------------- epilogue: bias, row sum-of-squares, normalize, store ---
    const float* bsm = (const float*)smem;
    float* rowsq = (float*)(smem + 512);
    #pragma unroll
    for (int mi = 0; mi < 2; ++mi)
        #pragma unroll
        for (int rp = 0; rp < 2; ++rp) {
            float s = 0.f;
            #pragma unroll
            for (int ni = 0; ni < 8; ++ni)
                #pragma unroll
                for (int c0 = 0; c0 < 2; ++c0) {
                    int col = wn * 64 + ni * 8 + tg * 2 + c0;
                    float x = c[mi][ni][rp * 2 + c0] + bsm[col];
                    c[mi][ni][rp * 2 + c0] = x;
                    s += x * x;
                }
            s += __shfl_xor_sync(0xFFFFFFFFu, s, 1);
            s += __shfl_xor_sync(0xFFFFFFFFu, s, 2);
            int row = wm * 32 + mi * 16 + gid + rp * 8;
            if (tg == 0) rowsq[wn * 128 + row] = s;
        }
    __syncthreads();

    unsigned char* dst = g_norm + (size_t)t * 32768 + (size_t)wn * 16384;
    #pragma unroll
    for (int mi = 0; mi < 2; ++mi)
        #pragma unroll
        for (int rp = 0; rp < 2; ++rp) {
            int row = wm * 32 + mi * 16 + gid + rp * 8;
            float tot = rowsq[row] + rowsq[128 + row];
            // pad rows (beyond compacted count) become exact zero vectors
            float mf = (t < 32 || rbase + row < cnt) ? 1.f : 0.f;
            float sc = mf / fmaxf(sqrtf(tot), 1e-12f);
            #pragma unroll
            for (int ni = 0; ni < 8; ++ni) {
                float x0 = c[mi][ni][rp * 2]     * sc;
                float x1 = c[mi][ni][rp * 2 + 1] * sc;
                __nv_bfloat162 p2 = __floats2bfloat162_rn(x0, x1);
                *(uint32_t*)(dst + sw128((uint32_t)(row * 128 + (ni * 8 + tg * 2) * 2))) =
                    *(uint32_t*)&p2;
            }
        }
}

// ============================ Kernel 2: MaxSim ============================
// grid 256 (= batch*2 pos/neg), block 256 (8 warps, each 16 doc rows).
// Loops over ceil(cnt/128) compacted doc tiles; clamps max at 0 when cnt<512
// (zero vectors from masked tokens contribute exactly 0 in the reference).
// smem: [0..1024) reduce buf fp32[8][32],
//       [1024..9216) Q tile: 2 chunks x [32r x 64k] SW128 (4KB each),
//       [9216) doc buf0 (2 x 16KB chunk images), [41984) doc buf1
__global__ void __launch_bounds__(256) k_maxsim(float* __restrict__ out)
{
    extern __shared__ __align__(1024) unsigned char smem[];
    uint32_t sb = smem_u32(smem);
    const int tid = threadIdx.x, wid = tid >> 5, lid = tid & 31;
    const int tg = lid & 3;
    const int b = blockIdx.x >> 1, s = blockIdx.x & 1;
    const int bs = s * 128 + b;
    const int cnt = g_cnt[bs];
    if (cnt == 0) { if (tid == 0) out[b * 2 + s] = 0.f; return; }
    const int nt = (cnt + 127) >> 7;           // 1..4 tiles
    const int tbase = 32 + bs * 4;

    // prologue: doc tile 0 via cp.async (32KB / 256 thr = 8 x 16B)
    {
        uint32_t dd = sb + 9216;
        const unsigned char* ds = g_norm + (size_t)tbase * 32768;
        #pragma unroll
        for (int u = 0; u < 8; ++u)
            CP_ASYNC16(dd + (tid + u * 256) * 16, ds + (size_t)(tid + u * 256) * 16);
        CP_COMMIT();
    }
    // Q slice: tile b>>2, rows (b&3)*32 (row-aligned to 8 -> valid SW128 sub-image)
    {
        const unsigned char* qsrc = g_norm + (size_t)(b >> 2) * 32768 + (size_t)(b & 3) * 4096;
        #pragma unroll
        for (int ch = 0; ch < 2; ++ch)
            ((uint4*)(smem + 1024 + ch * 4096))[tid] = ((const uint4*)(qsrc + ch * 16384))[tid];
    }

    const int lrow = (lid & 7) + ((lid >> 3) & 1) * 8;
    const int lhalf = lid >> 4;
    const int wr = wid * 16;                    // this warp's 16 doc rows

    float vmax[4][4];
    #pragma unroll
    for (int ni = 0; ni < 4; ++ni)
        #pragma unroll
        for (int r = 0; r < 4; ++r) vmax[ni][r] = -3.0e38f;

    for (int i = 0; i < nt; ++i) {
        const int buf = i & 1;
        CP_WAIT0();
        __syncthreads();
        if (i + 1 < nt) {
            uint32_t dd = sb + 9216 + (buf ^ 1) * 32768;
            const unsigned char* ds = g_norm + (size_t)(tbase + i + 1) * 32768;
            #pragma unroll
            for (int u = 0; u < 8; ++u)
                CP_ASYNC16(dd + (tid + u * 256) * 16, ds + (size_t)(tid + u * 256) * 16);
            CP_COMMIT();
        }

        float cc[4][4];
        #pragma unroll
        for (int ni = 0; ni < 4; ++ni)
            #pragma unroll
            for (int r = 0; r < 4; ++r) cc[ni][r] = 0.f;

        const uint32_t Db = sb + 9216 + buf * 32768;
        #pragma unroll
        for (int ks = 0; ks < 8; ++ks) {
            const int chunk = ks >> 2, kk = ks & 3;
            const int lseg = (kk * 2 + lhalf) * 16;
            uint32_t af[4];
            LDSM_X4(af[0], af[1], af[2], af[3],
                    Db + chunk * 16384 + sw128((uint32_t)((wr + lrow) * 128 + lseg)));
            uint32_t bf[4][2];
            #pragma unroll
            for (int nb = 0; nb < 2; ++nb) {
                int n = nb * 16 + lrow;
                uint32_t q0, q1, q2, q3;
                LDSM_X4(q0, q1, q2, q3,
                        sb + 1024 + chunk * 4096 + sw128((uint32_t)(n * 128 + lseg)));
                bf[nb * 2][0] = q0; bf[nb * 2][1] = q2;
                bf[nb * 2 + 1][0] = q1; bf[nb * 2 + 1][1] = q3;
            }
            #pragma unroll
            for (int ni = 0; ni < 4; ++ni)
                mma16816(cc[ni], af, bf[ni][0], bf[ni][1]);
        }
        #pragma unroll
        for (int ni = 0; ni < 4; ++ni)
            #pragma unroll
            for (int r = 0; r < 4; ++r)
                vmax[ni][r] = fmaxf(vmax[ni][r], cc[ni][r]);
        __syncthreads();
    }

    // per-query max over this warp's 16 doc rows
    float* red = (float*)smem;   // [8 warps][32 queries]
    #pragma unroll
    for (int ni = 0; ni < 4; ++ni)
        #pragma unroll
        for (int c0 = 0; c0 < 2; ++c0) {
            float m = fmaxf(vmax[ni][c0], vmax[ni][c0 + 2]);
            m = fmaxf(m, __shfl_xor_sync(0xFFFFFFFFu, m, 4));
            m = fmaxf(m, __shfl_xor_sync(0xFFFFFFFFu, m, 8));
            m = fmaxf(m, __shfl_xor_sync(0xFFFFFFFFu, m, 16));
            if ((lid >> 2) == 0) red[wid * 32 + ni * 8 + tg * 2 + c0] = m;
        }
    __syncthreads();
    if (tid < 32) {
        float m = red[tid];
        #pragma unroll
        for (int w = 1; w < 8; ++w) m = fmaxf(m, red[w * 32 + tid]);
        if (cnt < 512) m = fmaxf(m, 0.f);   // masked tokens are exact zero vectors
        #pragma unroll
        for (int off = 16; off; off >>= 1) m += __shfl_xor_sync(0xFFFFFFFFu, m, off);
        if (tid == 0) out[b * 2 + s] = m;
    }
}

// ============================ launch ============================
extern "C" void kernel_launch(void* const* d_in, const int* in_sizes, int n_in,
                              void* d_out, int out_size) {
    const float* qh  = (const float*)d_in[0];
    const float* pdh = (const float*)d_in[1];
    const float* ndh = (const float*)d_in[2];
    const float* W   = (const float*)d_in[3];
    const float* b   = (const float*)d_in[4];
    const int*   pdm = (const int*)d_in[5];
    const int*   ndm = (const int*)d_in[6];
    float* out = (float*)d_out;

    // dyn smem > 48KB needs an explicit opt-in
    cudaFuncSetAttribute(k_proj,   cudaFuncAttributeMaxDynamicSharedMemorySize, 67584);
    cudaFuncSetAttribute(k_maxsim, cudaFuncAttributeMaxDynamicSharedMemorySize, 74752);

    k_prep<<<640, 256>>>(W, pdm, ndm);
    k_proj<<<1056, 256, 67584>>>(qh, pdh, ndh, b);
    k_maxsim<<<256, 256, 74752>>>(out);
}